// round 3
// baseline (speedup 1.0000x reference)
#include <cuda_runtime.h>
#include <cstdint>

#define BB 256
#define NTOK 63
#define DD 128
#define EE 8
#define HH 256
#define T2 160
#define P1 132
#define P2 68

__device__ float g_gates[BB * 2];
__device__ int   g_eidx[BB * 2];
// Pre-split weights (3xTF32): hi = tf32(w), lo = tf32(w - hi)
__device__ float W1hi[EE * DD * HH];
__device__ float W1lo[EE * DD * HH];
__device__ float W2hi[EE * HH * T2];
__device__ float W2lo[EE * HH * T2];

__device__ __forceinline__ float tf32r(float v) {
    uint32_t u;
    asm("cvt.rna.tf32.f32 %0, %1;" : "=r"(u) : "f"(v));
    return __uint_as_float(u);
}

__device__ __forceinline__ void mma8(float* d, const uint32_t* a,
                                     uint32_t b0, uint32_t b1) {
    asm("mma.sync.aligned.m16n8k8.row.col.f32.tf32.tf32.f32 "
        "{%0,%1,%2,%3}, {%4,%5,%6,%7}, {%8,%9}, {%0,%1,%2,%3};"
        : "+f"(d[0]), "+f"(d[1]), "+f"(d[2]), "+f"(d[3])
        : "r"(a[0]), "r"(a[1]), "r"(a[2]), "r"(a[3]), "r"(b0), "r"(b1));
}

// ---------------- Weight hi/lo split (runs every launch; deterministic) ----------------
__global__ void split_kernel(const float* __restrict__ w1,
                             const float* __restrict__ w2) {
    int i = blockIdx.x * 256 + threadIdx.x;
    if (i < EE * DD * HH) {
        float v = w1[i], h = tf32r(v);
        W1hi[i] = h;
        W1lo[i] = tf32r(v - h);
    }
    if (i < EE * HH * T2) {
        float v = w2[i], h = tf32r(v);
        W2hi[i] = h;
        W2lo[i] = tf32r(v - h);
    }
}

// ---------------- Router ----------------
__global__ void router_kernel(const float* __restrict__ x,
                              const float* __restrict__ rw,
                              const float* __restrict__ rb) {
    int b = blockIdx.x;
    __shared__ float pooled[DD];
    __shared__ float logits[EE];
    int d = threadIdx.x;  // 128
    const float* xb = x + b * 64 * DD;
    float s = 0.f;
    #pragma unroll 4
    for (int n = 1; n < 64; n++) s += xb[n * DD + d];
    pooled[d] = s * (1.0f / 63.0f);
    __syncthreads();
    if (d < EE) {
        float l = rb[d];
        #pragma unroll 4
        for (int dd = 0; dd < DD; dd++) l += pooled[dd] * rw[dd * EE + d];
        logits[d] = l;
    }
    __syncthreads();
    if (d == 0) {
        float mx = logits[0];
        #pragma unroll
        for (int e = 1; e < EE; e++) mx = fmaxf(mx, logits[e]);
        float p[EE];
        float se = 0.f;
        #pragma unroll
        for (int e = 0; e < EE; e++) { p[e] = expf(logits[e] - mx); se += p[e]; }
        int i1 = 0;
        #pragma unroll
        for (int e = 1; e < EE; e++) if (p[e] > p[i1]) i1 = e;
        int i2 = (i1 == 0) ? 1 : 0;
        #pragma unroll
        for (int e = 0; e < EE; e++) if (e != i1 && p[e] > p[i2]) i2 = e;
        float inv = 1.f / se;
        g_eidx[b * 2 + 0]  = i1;
        g_gates[b * 2 + 0] = p[i1] * inv;
        g_eidx[b * 2 + 1]  = i2;
        g_gates[b * 2 + 1] = p[i2] * inv;
    }
}

// ---------------- Fused 2-expert FFN, tensor cores (3xTF32) ----------------
// One CTA per batch, 256 threads = 8 warps in a 4x2 grid over the 64-row tile.
// GEMM1 done in 4 column chunks of 64; h chunk (hi/lo split) lives in smem and
// is immediately consumed as the k-chunk of GEMM2 (accumulated in registers).
__global__ __launch_bounds__(256, 2) void moe_kernel(
    const float* __restrict__ x,
    const float* __restrict__ b1,
    const float* __restrict__ b2,
    float* __restrict__ out) {
    extern __shared__ float smem[];
    float* xhi = smem;                 // [64][P1]
    float* xlo = xhi + 64 * P1;        // [64][P1]
    float* hhi = xlo + 64 * P1;        // [64][P2] (one 64-col chunk)
    float* hlo = hhi + 64 * P2;        // [64][P2]

    int b = blockIdx.x, tid = threadIdx.x;

    // Load xa = x[b, 1:64, :] (row 63 zero-padded), split hi/lo into smem.
    const float* xb = x + b * 64 * DD + DD;
    for (int idx = tid; idx < 64 * DD; idx += 256) {
        int n = idx >> 7, d = idx & 127;
        float v = (n < NTOK) ? xb[n * DD + d] : 0.f;
        float h = tf32r(v);
        xhi[n * P1 + d] = h;
        xlo[n * P1 + d] = tf32r(v - h);
    }
    __syncthreads();

    const int wid = tid >> 5, lane = tid & 31;
    const int gid = lane >> 2, t4 = lane & 3;
    const int wm = wid & 3, wn = wid >> 2;
    const int m0 = wm * 16;
    const int ra = m0 + gid, rb = ra + 8;
    float* ob = out + b * NTOK * T2;

    for (int kk = 0; kk < 2; kk++) {
        const int   e = g_eidx[b * 2 + kk];
        const float g = g_gates[b * 2 + kk];

        float acc2[10][4];
        #pragma unroll
        for (int t = 0; t < 10; t++)
            #pragma unroll
            for (int j = 0; j < 4; j++) acc2[t][j] = 0.f;

        const float* w1h = W1hi + e * DD * HH;
        const float* w1l = W1lo + e * DD * HH;
        const float* w2h = W2hi + e * HH * T2;
        const float* w2l = W2lo + e * HH * T2;

        for (int ch = 0; ch < 4; ch++) {
            // ---- GEMM1 chunk: cols [ch*64, ch*64+64) ----
            float acc1[4][4];
            #pragma unroll
            for (int t = 0; t < 4; t++)
                #pragma unroll
                for (int j = 0; j < 4; j++) acc1[t][j] = 0.f;

            #pragma unroll 4
            for (int k8 = 0; k8 < 16; k8++) {
                int k0 = k8 * 8;
                uint32_t ah[4], al[4];
                ah[0] = __float_as_uint(xhi[ra * P1 + k0 + t4]);
                ah[1] = __float_as_uint(xhi[rb * P1 + k0 + t4]);
                ah[2] = __float_as_uint(xhi[ra * P1 + k0 + t4 + 4]);
                ah[3] = __float_as_uint(xhi[rb * P1 + k0 + t4 + 4]);
                al[0] = __float_as_uint(xlo[ra * P1 + k0 + t4]);
                al[1] = __float_as_uint(xlo[rb * P1 + k0 + t4]);
                al[2] = __float_as_uint(xlo[ra * P1 + k0 + t4 + 4]);
                al[3] = __float_as_uint(xlo[rb * P1 + k0 + t4 + 4]);
                const float* bh = w1h + (k0 + t4) * HH;
                const float* bl = w1l + (k0 + t4) * HH;
                #pragma unroll
                for (int t = 0; t < 4; t++) {
                    int n0 = ch * 64 + wn * 32 + t * 8 + gid;
                    uint32_t bh0 = __float_as_uint(bh[n0]);
                    uint32_t bh1 = __float_as_uint(bh[4 * HH + n0]);
                    uint32_t bl0 = __float_as_uint(bl[n0]);
                    uint32_t bl1 = __float_as_uint(bl[4 * HH + n0]);
                    mma8(acc1[t], ah, bh0, bh1);
                    mma8(acc1[t], ah, bl0, bl1);
                    mma8(acc1[t], al, bh0, bh1);
                }
            }
            __syncthreads();  // prior GEMM2 readers of h chunk are done

            // epilogue: bias + relu + hi/lo split -> h chunk smem
            #pragma unroll
            for (int t = 0; t < 4; t++) {
                int cl0 = wn * 32 + t * 8 + 2 * t4;
                int jg = e * HH + ch * 64 + cl0;
                float bv0 = b1[jg], bv1 = b1[jg + 1];
                float v00 = fmaxf(acc1[t][0] + bv0, 0.f);
                float v01 = fmaxf(acc1[t][1] + bv1, 0.f);
                float v10 = fmaxf(acc1[t][2] + bv0, 0.f);
                float v11 = fmaxf(acc1[t][3] + bv1, 0.f);
                float h;
                h = tf32r(v00); hhi[ra * P2 + cl0]     = h; hlo[ra * P2 + cl0]     = tf32r(v00 - h);
                h = tf32r(v01); hhi[ra * P2 + cl0 + 1] = h; hlo[ra * P2 + cl0 + 1] = tf32r(v01 - h);
                h = tf32r(v10); hhi[rb * P2 + cl0]     = h; hlo[rb * P2 + cl0]     = tf32r(v10 - h);
                h = tf32r(v11); hhi[rb * P2 + cl0 + 1] = h; hlo[rb * P2 + cl0 + 1] = tf32r(v11 - h);
            }
            __syncthreads();

            // ---- GEMM2 partial: k rows [ch*64, ch*64+64) ----
            #pragma unroll 2
            for (int k8 = 0; k8 < 8; k8++) {
                int k0 = k8 * 8;
                uint32_t ah[4], al[4];
                ah[0] = __float_as_uint(hhi[ra * P2 + k0 + t4]);
                ah[1] = __float_as_uint(hhi[rb * P2 + k0 + t4]);
                ah[2] = __float_as_uint(hhi[ra * P2 + k0 + t4 + 4]);
                ah[3] = __float_as_uint(hhi[rb * P2 + k0 + t4 + 4]);
                al[0] = __float_as_uint(hlo[ra * P2 + k0 + t4]);
                al[1] = __float_as_uint(hlo[rb * P2 + k0 + t4]);
                al[2] = __float_as_uint(hlo[ra * P2 + k0 + t4 + 4]);
                al[3] = __float_as_uint(hlo[rb * P2 + k0 + t4 + 4]);
                const float* bh = w2h + (ch * 64 + k0 + t4) * T2;
                const float* bl = w2l + (ch * 64 + k0 + t4) * T2;
                #pragma unroll
                for (int t = 0; t < 10; t++) {
                    int n0 = wn * 80 + t * 8 + gid;
                    uint32_t bh0 = __float_as_uint(bh[n0]);
                    uint32_t bh1 = __float_as_uint(bh[4 * T2 + n0]);
                    uint32_t bl0 = __float_as_uint(bl[n0]);
                    uint32_t bl1 = __float_as_uint(bl[4 * T2 + n0]);
                    mma8(acc2[t], ah, bh0, bh1);
                    mma8(acc2[t], ah, bl0, bl1);
                    mma8(acc2[t], al, bh0, bh1);
                }
            }
        }

        // ---- output epilogue: bias, gate, store/accumulate ----
        #pragma unroll
        for (int t = 0; t < 10; t++) {
            int n0 = wn * 80 + t * 8 + 2 * t4;
            float bv0 = b2[e * T2 + n0], bv1 = b2[e * T2 + n0 + 1];
            float v00 = g * (acc2[t][0] + bv0), v01 = g * (acc2[t][1] + bv1);
            float v10 = g * (acc2[t][2] + bv0), v11 = g * (acc2[t][3] + bv1);
            float* p0 = ob + ra * T2 + n0;
            if (kk == 0) { p0[0] = v00; p0[1] = v01; }
            else         { p0[0] += v00; p0[1] += v01; }
            if (rb < NTOK) {
                float* p1 = ob + rb * T2 + n0;
                if (kk == 0) { p1[0] = v10; p1[1] = v11; }
                else         { p1[0] += v10; p1[1] += v11; }
            }
        }
    }
}

extern "C" void kernel_launch(void* const* d_in, const int* in_sizes, int n_in,
                              void* d_out, int out_size) {
    const float* x  = (const float*)d_in[0];
    const float* rw = (const float*)d_in[1];
    const float* rb = (const float*)d_in[2];
    const float* w1 = (const float*)d_in[3];
    const float* b1 = (const float*)d_in[4];
    const float* w2 = (const float*)d_in[5];
    const float* b2 = (const float*)d_in[6];
    float* out = (float*)d_out;

    split_kernel<<<(EE * HH * T2 + 255) / 256, 256>>>(w1, w2);
    router_kernel<<<BB, 128>>>(x, rw, rb);

    const int smem_bytes = (2 * 64 * P1 + 2 * 64 * P2) * (int)sizeof(float);
    cudaFuncSetAttribute(moe_kernel, cudaFuncAttributeMaxDynamicSharedMemorySize,
                         smem_bytes);
    moe_kernel<<<BB, 256, smem_bytes>>>(x, b1, b2, out);
}

// round 5
// speedup vs baseline: 2.8630x; 2.8630x over previous
#include <cuda_runtime.h>
#include <cuda_bf16.h>
#include <cstdint>

#define BB 256
#define NTOK 63
#define DD 128
#define EE 8
#define HH 256
#define T2 160

// ---------------- device globals ----------------
__device__ float g_gates[BB * 2];
__device__ int   g_eidx[BB * 2];
// W1T[e][h][d] (k contiguous), bf16 hi/lo
__device__ __nv_bfloat16 W1Th[EE * HH * DD];
__device__ __nv_bfloat16 W1Tl[EE * HH * DD];
// W2T[e][kchunk][o][64], bf16 hi/lo
__device__ __nv_bfloat16 W2Th[EE * 4 * T2 * 64];
__device__ __nv_bfloat16 W2Tl[EE * 4 * T2 * 64];

// ---------------- smem layout (bytes) ----------------
// padded row strides: +16B so ldmatrix 8-row reads are conflict-free
#define SX 272      // x rows: 128 bf16 + pad
#define SH 528      // h rows: 256 bf16 + pad
#define SB 144      // B2 rows: 64 bf16 + pad
#define SM_XH 0
#define SM_XL 17408
#define SM_HH 34816
#define SM_HL 68608
#define SM_B1 102400          // 2 buffers x 34816 (hi 17408 + lo 17408)
#define SM_B2D 172032         // dedicated B2 buffer (hi 23040 + lo 23040)
#define SM_BIAS 218112        // 160 floats
#define SM_TOT 218752

// ---------------- PTX helpers ----------------
__device__ __forceinline__ uint32_t smem_u32(const void* p) {
    uint32_t a;
    asm("{ .reg .u64 t; cvta.to.shared.u64 t, %1; cvt.u32.u64 %0, t; }" : "=r"(a) : "l"(p));
    return a;
}
__device__ __forceinline__ void ldsm4(uint32_t* r, uint32_t addr) {
    asm volatile("ldmatrix.sync.aligned.m8n8.x4.shared.b16 {%0,%1,%2,%3}, [%4];"
        : "=r"(r[0]), "=r"(r[1]), "=r"(r[2]), "=r"(r[3]) : "r"(addr));
}
__device__ __forceinline__ void mma16(float* d, const uint32_t* a, uint32_t b0, uint32_t b1) {
    asm volatile("mma.sync.aligned.m16n8k16.row.col.f32.bf16.bf16.f32 "
        "{%0,%1,%2,%3}, {%4,%5,%6,%7}, {%8,%9}, {%0,%1,%2,%3};"
        : "+f"(d[0]), "+f"(d[1]), "+f"(d[2]), "+f"(d[3])
        : "r"(a[0]), "r"(a[1]), "r"(a[2]), "r"(a[3]), "r"(b0), "r"(b1));
}
__device__ __forceinline__ void cp16(uint32_t dst, const void* src) {
    asm volatile("cp.async.cg.shared.global [%0], [%1], 16;" :: "r"(dst), "l"(src));
}
#define CP_COMMIT() asm volatile("cp.async.commit_group;" ::: "memory")
#define CP_WAIT(n)  asm volatile("cp.async.wait_group %0;" :: "n"(n) : "memory")

// ---------------- prep: transpose + bf16 hi/lo split ----------------
__global__ void prep_w1(const float* __restrict__ w1) {
    __shared__ float t[32][33];
    int e = blockIdx.z, d0 = blockIdx.x * 32, h0 = blockIdx.y * 32;
    int tx = threadIdx.x, ty = threadIdx.y;
    #pragma unroll
    for (int i = 0; i < 4; i++)
        t[ty + 8 * i][tx] = w1[(e * DD + d0 + ty + 8 * i) * HH + h0 + tx];
    __syncthreads();
    #pragma unroll
    for (int i = 0; i < 4; i++) {
        float v = t[tx][ty + 8 * i];
        int idx = (e * HH + h0 + ty + 8 * i) * DD + d0 + tx;
        __nv_bfloat16 h = __float2bfloat16(v);
        W1Th[idx] = h;
        W1Tl[idx] = __float2bfloat16(v - __bfloat162float(h));
    }
}
__global__ void prep_w2(const float* __restrict__ w2) {
    __shared__ float t[32][33];
    int e = blockIdx.z, k0 = blockIdx.x * 32, o0 = blockIdx.y * 32;
    int tx = threadIdx.x, ty = threadIdx.y;
    #pragma unroll
    for (int i = 0; i < 4; i++)
        t[ty + 8 * i][tx] = w2[(e * HH + k0 + ty + 8 * i) * T2 + o0 + tx];
    __syncthreads();
    #pragma unroll
    for (int i = 0; i < 4; i++) {
        int hd = k0 + tx, o = o0 + ty + 8 * i;
        float v = t[tx][ty + 8 * i];
        int idx = ((e * 4 + (hd >> 6)) * T2 + o) * 64 + (hd & 63);
        __nv_bfloat16 h = __float2bfloat16(v);
        W2Th[idx] = h;
        W2Tl[idx] = __float2bfloat16(v - __bfloat162float(h));
    }
}

// ---------------- router ----------------
__global__ void router_kernel(const float* __restrict__ x,
                              const float* __restrict__ rw,
                              const float* __restrict__ rb) {
    int b = blockIdx.x;
    __shared__ float pooled[DD];
    __shared__ float logits[EE];
    int d = threadIdx.x;
    const float* xb = x + b * 64 * DD;
    float s = 0.f;
    #pragma unroll 4
    for (int n = 1; n < 64; n++) s += xb[n * DD + d];
    pooled[d] = s * (1.0f / 63.0f);
    __syncthreads();
    if (d < EE) {
        float l = rb[d];
        #pragma unroll 4
        for (int dd = 0; dd < DD; dd++) l += pooled[dd] * rw[dd * EE + d];
        logits[d] = l;
    }
    __syncthreads();
    if (d == 0) {
        float mx = logits[0];
        #pragma unroll
        for (int e = 1; e < EE; e++) mx = fmaxf(mx, logits[e]);
        float p[EE];
        float se = 0.f;
        #pragma unroll
        for (int e = 0; e < EE; e++) { p[e] = expf(logits[e] - mx); se += p[e]; }
        int i1 = 0;
        #pragma unroll
        for (int e = 1; e < EE; e++) if (p[e] > p[i1]) i1 = e;
        int i2 = (i1 == 0) ? 1 : 0;
        #pragma unroll
        for (int e = 0; e < EE; e++) if (e != i1 && p[e] > p[i2]) i2 = e;
        float inv = 1.f / se;
        g_eidx[b * 2 + 0]  = i1;
        g_gates[b * 2 + 0] = p[i1] * inv;
        g_eidx[b * 2 + 1]  = i2;
        g_gates[b * 2 + 1] = p[i2] * inv;
    }
}

// ---------------- cp.async tile loaders ----------------
__device__ __forceinline__ void load_b1(uint32_t sb, int e, int ch, int buf, int tid) {
    const char* sh = (const char*)(W1Th + (e * HH + ch * 64) * DD);
    const char* sl = (const char*)(W1Tl + (e * HH + ch * 64) * DD);
    uint32_t dh = sb + SM_B1 + buf * 34816;
    #pragma unroll
    for (int i = 0; i < 4; i++) {
        int c = tid + i * 256;
        uint32_t off = (uint32_t)(c >> 4) * SX + (uint32_t)(c & 15) * 16;
        cp16(dh + off, sh + c * 16);
        cp16(dh + 17408 + off, sl + c * 16);
    }
}
__device__ __forceinline__ void load_b2(uint32_t sb, int e, int kc, uint32_t dsto, int tid) {
    const char* sh = (const char*)(W2Th + (e * 4 + kc) * T2 * 64);
    const char* sl = (const char*)(W2Tl + (e * 4 + kc) * T2 * 64);
    #pragma unroll
    for (int i = 0; i < 5; i++) {
        int c = tid + i * 256;
        uint32_t off = (uint32_t)(c >> 3) * SB + (uint32_t)(c & 7) * 16;
        cp16(sb + dsto + off, sh + c * 16);
        cp16(sb + dsto + 23040 + off, sl + c * 16);
    }
}

// ---------------- main fused kernel ----------------
__global__ __launch_bounds__(256, 1) void moe_kernel(
    const float* __restrict__ x,
    const float* __restrict__ b1g,
    const float* __restrict__ b2g,
    float* __restrict__ out) {
    extern __shared__ char smem[];
    uint32_t sb = smem_u32(smem);
    int tid = threadIdx.x, wid = tid >> 5, lane = tid & 31;
    int b = blockIdx.x;
    const int wm = wid & 3, wn = wid >> 2;
    const int t = lane >> 3, r8 = lane & 7, q = lane >> 2, p2 = (lane & 3) * 2;

    const int e0 = g_eidx[b * 2 + 0], e1 = g_eidx[b * 2 + 1];
    const float gt0 = g_gates[b * 2 + 0], gt1 = g_gates[b * 2 + 1];

    // combined output bias: gt0*b2[e0] + gt1*b2[e1]
    if (tid < T2)
        ((float*)(smem + SM_BIAS))[tid] =
            gt0 * __ldg(b2g + e0 * T2 + tid) + gt1 * __ldg(b2g + e1 * T2 + tid);

    // zero pad row 63 of x tiles
    if (tid < 17) {
        *(uint4*)(smem + SM_XH + 63 * SX + tid * 16) = make_uint4(0, 0, 0, 0);
        *(uint4*)(smem + SM_XL + 63 * SX + tid * 16) = make_uint4(0, 0, 0, 0);
    }
    // fill x rows 0..62 (token n -> x[b][n+1]), bf16 hi/lo split
    if (tid < 252) {
        int r = tid >> 2, seg = (tid & 3) * 32;
        const float4* xr = (const float4*)(x + (b * 64 + 1 + r) * DD + seg);
        #pragma unroll
        for (int j = 0; j < 8; j++) {
            float4 v = xr[j];
            int d = seg + j * 4;
            __nv_bfloat16 h0 = __float2bfloat16(v.x), h1 = __float2bfloat16(v.y);
            __nv_bfloat16 h2 = __float2bfloat16(v.z), h3 = __float2bfloat16(v.w);
            __nv_bfloat16 l0 = __float2bfloat16(v.x - __bfloat162float(h0));
            __nv_bfloat16 l1 = __float2bfloat16(v.y - __bfloat162float(h1));
            __nv_bfloat16 l2 = __float2bfloat16(v.z - __bfloat162float(h2));
            __nv_bfloat16 l3 = __float2bfloat16(v.w - __bfloat162float(h3));
            uint32_t o = r * SX + d * 2;
            *(__nv_bfloat162*)(smem + SM_XH + o)     = __halves2bfloat162(h0, h1);
            *(__nv_bfloat162*)(smem + SM_XH + o + 4) = __halves2bfloat162(h2, h3);
            *(__nv_bfloat162*)(smem + SM_XL + o)     = __halves2bfloat162(l0, l1);
            *(__nv_bfloat162*)(smem + SM_XL + o + 4) = __halves2bfloat162(l2, l3);
        }
    }
    __syncthreads();

    load_b1(sb, e0, 0, 0, tid); CP_COMMIT();
    load_b1(sb, e0, 1, 1, tid); CP_COMMIT();

    // x A-fragments: rows wm*16..+15, all k (held both experts)
    uint32_t xah[8][4], xal[8][4];
    {
        uint32_t ro = (uint32_t)(wm * 16 + (t & 1) * 8 + r8) * SX + (uint32_t)((t >> 1) * 8) * 2;
        #pragma unroll
        for (int ks = 0; ks < 8; ks++) {
            ldsm4(xah[ks], sb + SM_XH + ro + ks * 32);
            ldsm4(xal[ks], sb + SM_XL + ro + ks * 32);
        }
    }

    float acc2[10][4];
    #pragma unroll
    for (int nt = 0; nt < 10; nt++)
        #pragma unroll
        for (int j = 0; j < 4; j++) acc2[nt][j] = 0.f;

    for (int ee = 0; ee < 2; ee++) {
        const int   e = ee ? e1 : e0;
        const float g = ee ? gt1 : gt0;

        // ---- phase A: GEMM1 in 4 n-chunks of 64, double-buffered B1 ----
        for (int ch = 0; ch < 4; ch++) {
            CP_WAIT(1);
            __syncthreads();
            float acc1[4][4];
            #pragma unroll
            for (int nt = 0; nt < 4; nt++)
                #pragma unroll
                for (int j = 0; j < 4; j++) acc1[nt][j] = 0.f;

            uint32_t bbase = sb + SM_B1 + (uint32_t)(ch & 1) * 34816 +
                             (uint32_t)(wn * 32 + (t >> 1) * 8 + r8) * SX +
                             (uint32_t)((t & 1) * 8) * 2;
            #pragma unroll
            for (int ks = 0; ks < 8; ks++) {
                #pragma unroll
                for (int ntp = 0; ntp < 2; ntp++) {
                    uint32_t a = bbase + (uint32_t)(ntp * 16) * SX + ks * 32;
                    uint32_t bh[4], bl[4];
                    ldsm4(bh, a);
                    ldsm4(bl, a + 17408);
                    mma16(acc1[ntp * 2],     xah[ks], bh[0], bh[1]);
                    mma16(acc1[ntp * 2],     xal[ks], bh[0], bh[1]);
                    mma16(acc1[ntp * 2],     xah[ks], bl[0], bl[1]);
                    mma16(acc1[ntp * 2 + 1], xah[ks], bh[2], bh[3]);
                    mma16(acc1[ntp * 2 + 1], xal[ks], bh[2], bh[3]);
                    mma16(acc1[ntp * 2 + 1], xah[ks], bl[2], bl[3]);
                }
            }
            // epilogue: bias + relu + gate, bf16 hi/lo -> h smem
            #pragma unroll
            for (int nt = 0; nt < 4; nt++) {
                int hcol = ch * 64 + wn * 32 + nt * 8 + p2;
                float bv0 = __ldg(b1g + e * HH + hcol);
                float bv1 = __ldg(b1g + e * HH + hcol + 1);
                int r0 = wm * 16 + q;
                float v00 = g * fmaxf(acc1[nt][0] + bv0, 0.f);
                float v01 = g * fmaxf(acc1[nt][1] + bv1, 0.f);
                float v10 = g * fmaxf(acc1[nt][2] + bv0, 0.f);
                float v11 = g * fmaxf(acc1[nt][3] + bv1, 0.f);
                __nv_bfloat16 a0 = __float2bfloat16(v00), a1 = __float2bfloat16(v01);
                __nv_bfloat16 c0 = __float2bfloat16(v10), c1 = __float2bfloat16(v11);
                uint32_t o0 = (uint32_t)r0 * SH + hcol * 2;
                uint32_t o1 = (uint32_t)(r0 + 8) * SH + hcol * 2;
                *(__nv_bfloat162*)(smem + SM_HH + o0) = __halves2bfloat162(a0, a1);
                *(__nv_bfloat162*)(smem + SM_HH + o1) = __halves2bfloat162(c0, c1);
                *(__nv_bfloat162*)(smem + SM_HL + o0) = __halves2bfloat162(
                    __float2bfloat16(v00 - __bfloat162float(a0)),
                    __float2bfloat16(v01 - __bfloat162float(a1)));
                *(__nv_bfloat162*)(smem + SM_HL + o1) = __halves2bfloat162(
                    __float2bfloat16(v10 - __bfloat162float(c0)),
                    __float2bfloat16(v11 - __bfloat162float(c1)));
            }
            __syncthreads();
            if (ch < 2)       load_b1(sb, e, ch + 2, ch & 1, tid);
            else if (ch == 2) load_b2(sb, e, 0, SM_B2D, tid);
            else              load_b2(sb, e, 1, SM_B1, tid);
            CP_COMMIT();
        }

        // ---- phase B: GEMM2 in 4 k-chunks of 64, buffers ded/B1-region ----
        for (int kc = 0; kc < 4; kc++) {
            if (kc == 3) { CP_WAIT(0); } else { CP_WAIT(1); }
            __syncthreads();
            uint32_t bufo = (kc & 1) ? (uint32_t)SM_B1 : (uint32_t)SM_B2D;

            uint32_t hah[4][4], hal[4][4];
            {
                uint32_t ro = sb + SM_HH +
                    (uint32_t)(wm * 16 + (t & 1) * 8 + r8) * SH +
                    (uint32_t)(kc * 64 + (t >> 1) * 8) * 2;
                #pragma unroll
                for (int ks = 0; ks < 4; ks++) {
                    ldsm4(hah[ks], ro + ks * 32);
                    ldsm4(hal[ks], ro + ks * 32 + (SM_HL - SM_HH));
                }
            }
            uint32_t bbase = sb + bufo +
                (uint32_t)(wn * 80 + (t >> 1) * 8 + r8) * SB +
                (uint32_t)((t & 1) * 8) * 2;
            #pragma unroll
            for (int ks = 0; ks < 4; ks++) {
                #pragma unroll
                for (int ntp = 0; ntp < 5; ntp++) {
                    uint32_t a = bbase + (uint32_t)(ntp * 16) * SB + ks * 32;
                    uint32_t bh[4], bl[4];
                    ldsm4(bh, a);
                    ldsm4(bl, a + 23040);
                    mma16(acc2[ntp * 2],     hah[ks], bh[0], bh[1]);
                    mma16(acc2[ntp * 2],     hal[ks], bh[0], bh[1]);
                    mma16(acc2[ntp * 2],     hah[ks], bl[0], bl[1]);
                    mma16(acc2[ntp * 2 + 1], hah[ks], bh[2], bh[3]);
                    mma16(acc2[ntp * 2 + 1], hal[ks], bh[2], bh[3]);
                    mma16(acc2[ntp * 2 + 1], hah[ks], bl[2], bl[3]);
                }
            }
            __syncthreads();
            if (kc < 2) {
                load_b2(sb, e, kc + 2, (kc & 1) ? (uint32_t)SM_B1 : (uint32_t)SM_B2D, tid);
                CP_COMMIT();
            } else if (kc == 3 && ee == 0) {
                load_b1(sb, e1, 0, 0, tid); CP_COMMIT();
                load_b1(sb, e1, 1, 1, tid); CP_COMMIT();
            }
        }
    }

    // ---- final epilogue ----
    const float* bc = (const float*)(smem + SM_BIAS);
    int r0 = wm * 16 + q;
    #pragma unroll
    for (int nt = 0; nt < 10; nt++) {
        int col = wn * 80 + nt * 8 + p2;
        float bv0 = bc[col], bv1 = bc[col + 1];
        if (r0 < NTOK) {
            float2 v = make_float2(acc2[nt][0] + bv0, acc2[nt][1] + bv1);
            *(float2*)(out + (b * NTOK + r0) * T2 + col) = v;
        }
        if (r0 + 8 < NTOK) {
            float2 v = make_float2(acc2[nt][2] + bv0, acc2[nt][3] + bv1);
            *(float2*)(out + (b * NTOK + r0 + 8) * T2 + col) = v;
        }
    }
}

extern "C" void kernel_launch(void* const* d_in, const int* in_sizes, int n_in,
                              void* d_out, int out_size) {
    const float* x  = (const float*)d_in[0];
    const float* rw = (const float*)d_in[1];
    const float* rb = (const float*)d_in[2];
    const float* w1 = (const float*)d_in[3];
    const float* b1 = (const float*)d_in[4];
    const float* w2 = (const float*)d_in[5];
    const float* b2 = (const float*)d_in[6];
    float* out = (float*)d_out;

    prep_w1<<<dim3(DD / 32, HH / 32, EE), dim3(32, 8)>>>(w1);
    prep_w2<<<dim3(HH / 32, T2 / 32, EE), dim3(32, 8)>>>(w2);
    router_kernel<<<BB, 128>>>(x, rw, rb);

    cudaFuncSetAttribute(moe_kernel, cudaFuncAttributeMaxDynamicSharedMemorySize, SM_TOT);
    moe_kernel<<<BB, 256, SM_TOT>>>(x, b1, b2, out);
}

// round 6
// speedup vs baseline: 2.9372x; 1.0259x over previous
#include <cuda_runtime.h>
#include <cuda_bf16.h>
#include <cstdint>

#define BB 256
#define NTOK 63
#define DD 128
#define EE 8
#define HH 256
#define T2 160

// ---------------- device globals ----------------
__device__ float g_gates[BB * 2];
__device__ int   g_eidx[BB * 2];
__device__ __nv_bfloat16 W1Th[EE * HH * DD];   // [e][hcol][d] k-contig
__device__ __nv_bfloat16 W1Tl[EE * HH * DD];
__device__ __nv_bfloat16 W2Th[EE * 4 * T2 * 64]; // [e][kchunk][o][64]
__device__ __nv_bfloat16 W2Tl[EE * 4 * T2 * 64];

// ---------------- smem layout (bytes), XOR-swizzled tiles ----------------
#define SM_XH  0        // x hi: 64 rows x 256B (swz)
#define SM_XL  16384
#define SM_HH  32768    // h chunk hi: 64 rows x 128B (swz)
#define SM_HL  40960
#define SM_B1H 49152    // W1 chunk hi: 64 rows x 256B (swz)
#define SM_B1L 65536
#define SM_B2A 81920    // W2 k16 tile A: hi 160x48B, lo +7680
#define SM_B2B 97280    // W2 k16 tile B
#define SM_BIAS 112640  // 160 floats
#define SM_TOT 113664

// ---------------- PTX helpers ----------------
__device__ __forceinline__ uint32_t smem_u32(const void* p) {
    uint32_t a;
    asm("{ .reg .u64 t; cvta.to.shared.u64 t, %1; cvt.u32.u64 %0, t; }" : "=r"(a) : "l"(p));
    return a;
}
__device__ __forceinline__ void ldsm4(uint32_t* r, uint32_t addr) {
    asm volatile("ldmatrix.sync.aligned.m8n8.x4.shared.b16 {%0,%1,%2,%3}, [%4];"
        : "=r"(r[0]), "=r"(r[1]), "=r"(r[2]), "=r"(r[3]) : "r"(addr));
}
__device__ __forceinline__ void mma16(float* d, const uint32_t* a, uint32_t b0, uint32_t b1) {
    asm volatile("mma.sync.aligned.m16n8k16.row.col.f32.bf16.bf16.f32 "
        "{%0,%1,%2,%3}, {%4,%5,%6,%7}, {%8,%9}, {%0,%1,%2,%3};"
        : "+f"(d[0]), "+f"(d[1]), "+f"(d[2]), "+f"(d[3])
        : "r"(a[0]), "r"(a[1]), "r"(a[2]), "r"(a[3]), "r"(b0), "r"(b1));
}
__device__ __forceinline__ void cp16(uint32_t dst, const void* src) {
    asm volatile("cp.async.cg.shared.global [%0], [%1], 16;" :: "r"(dst), "l"(src));
}
#define CP_COMMIT() asm volatile("cp.async.commit_group;" ::: "memory")
#define CP_WAIT(n)  asm volatile("cp.async.wait_group %0;" :: "n"(n) : "memory")

// ---------------- prep (fused): transpose + bf16 hi/lo split ----------------
__global__ void prep_w(const float* __restrict__ w1, const float* __restrict__ w2) {
    __shared__ float t[32][33];
    int e = blockIdx.z, bx = blockIdx.x;
    int tx = threadIdx.x, ty = threadIdx.y;
    if (bx < 32) {
        int d0 = (bx & 3) * 32, h0 = (bx >> 2) * 32;
        #pragma unroll
        for (int i = 0; i < 4; i++)
            t[ty + 8 * i][tx] = w1[(e * DD + d0 + ty + 8 * i) * HH + h0 + tx];
        __syncthreads();
        #pragma unroll
        for (int i = 0; i < 4; i++) {
            float v = t[tx][ty + 8 * i];
            int idx = (e * HH + h0 + ty + 8 * i) * DD + d0 + tx;
            __nv_bfloat16 h = __float2bfloat16(v);
            W1Th[idx] = h;
            W1Tl[idx] = __float2bfloat16(v - __bfloat162float(h));
        }
    } else {
        int i2 = bx - 32;
        int k0 = (i2 & 7) * 32, o0 = (i2 >> 3) * 32;
        #pragma unroll
        for (int i = 0; i < 4; i++)
            t[ty + 8 * i][tx] = w2[(e * HH + k0 + ty + 8 * i) * T2 + o0 + tx];
        __syncthreads();
        #pragma unroll
        for (int i = 0; i < 4; i++) {
            int hd = k0 + tx, o = o0 + ty + 8 * i;
            float v = t[tx][ty + 8 * i];
            int idx = ((e * 4 + (hd >> 6)) * T2 + o) * 64 + (hd & 63);
            __nv_bfloat16 h = __float2bfloat16(v);
            W2Th[idx] = h;
            W2Tl[idx] = __float2bfloat16(v - __bfloat162float(h));
        }
    }
}

// ---------------- router ----------------
__global__ void router_kernel(const float* __restrict__ x,
                              const float* __restrict__ rw,
                              const float* __restrict__ rb) {
    int b = blockIdx.x;
    __shared__ float pooled[DD];
    __shared__ float logits[EE];
    int d = threadIdx.x;
    const float* xb = x + b * 64 * DD;
    float s = 0.f;
    #pragma unroll 4
    for (int n = 1; n < 64; n++) s += xb[n * DD + d];
    pooled[d] = s * (1.0f / 63.0f);
    __syncthreads();
    if (d < EE) {
        float l = rb[d];
        #pragma unroll 4
        for (int dd = 0; dd < DD; dd++) l += pooled[dd] * rw[dd * EE + d];
        logits[d] = l;
    }
    __syncthreads();
    if (d == 0) {
        float mx = logits[0];
        #pragma unroll
        for (int e = 1; e < EE; e++) mx = fmaxf(mx, logits[e]);
        float p[EE];
        float se = 0.f;
        #pragma unroll
        for (int e = 0; e < EE; e++) { p[e] = expf(logits[e] - mx); se += p[e]; }
        int i1 = 0;
        #pragma unroll
        for (int e = 1; e < EE; e++) if (p[e] > p[i1]) i1 = e;
        int i2 = (i1 == 0) ? 1 : 0;
        #pragma unroll
        for (int e = 0; e < EE; e++) if (e != i1 && p[e] > p[i2]) i2 = e;
        float inv = 1.f / se;
        g_eidx[b * 2 + 0]  = i1;
        g_gates[b * 2 + 0] = p[i1] * inv;
        g_eidx[b * 2 + 1]  = i2;
        g_gates[b * 2 + 1] = p[i2] * inv;
    }
}

// ---------------- cp.async tile loaders (empty-commit safe past ch>=8) ----------------
__device__ __forceinline__ void load_b1t(uint32_t sb, int ch, int e0, int e1, int tid) {
    if (ch >= 8) return;
    int e = (ch >> 2) ? e1 : e0;
    int c4 = ch & 3;
    const char* sh = (const char*)(W1Th + (e * HH + c4 * 64) * DD);
    const char* sl = (const char*)(W1Tl + (e * HH + c4 * 64) * DD);
    #pragma unroll
    for (int i = 0; i < 4; i++) {
        int c = tid + i * 256;
        int row = c >> 4, seg = c & 15;
        uint32_t d = (uint32_t)row * 256 + (uint32_t)((seg ^ (row & 7)) << 4);
        cp16(sb + SM_B1H + d, sh + c * 16);
        cp16(sb + SM_B1L + d, sl + c * 16);
    }
}
__device__ __forceinline__ void load_b2t(uint32_t sb, int ch, int sub, uint32_t buf,
                                         int e0, int e1, int tid) {
    if (ch >= 8) return;
    int e = (ch >> 2) ? e1 : e0;
    int c4 = ch & 3;
    const char* sh = (const char*)(W2Th + (e * 4 + c4) * T2 * 64) + sub * 32;
    const char* sl = (const char*)(W2Tl + (e * 4 + c4) * T2 * 64) + sub * 32;
    #pragma unroll
    for (int i = 0; i < 2; i++) {
        int c = tid + i * 256;
        if (c < 320) {
            int row = c >> 1, seg = c & 1;
            uint32_t d = buf + (uint32_t)row * 48 + (uint32_t)seg * 16;
            cp16(sb + d, sh + row * 128 + seg * 16);
            cp16(sb + d + 7680, sl + row * 128 + seg * 16);
        }
    }
}

// ---------------- main fused kernel: 2 CTAs/SM ----------------
__global__ __launch_bounds__(256, 2) void moe_kernel(
    const float* __restrict__ x,
    const float* __restrict__ b1g,
    const float* __restrict__ b2g,
    float* __restrict__ out) {
    extern __shared__ char smem[];
    uint32_t sb = smem_u32(smem);
    int tid = threadIdx.x, wid = tid >> 5, lane = tid & 31;
    int b = blockIdx.x;
    const int wm = wid & 3, wn = wid >> 2;
    const int t = lane >> 3, r8 = lane & 7, q = lane >> 2, p2 = (lane & 3) * 2;

    const int e0 = g_eidx[b * 2 + 0], e1 = g_eidx[b * 2 + 1];
    const float gt0 = g_gates[b * 2 + 0], gt1 = g_gates[b * 2 + 1];

    if (tid < T2)
        ((float*)(smem + SM_BIAS))[tid] =
            gt0 * __ldg(b2g + e0 * T2 + tid) + gt1 * __ldg(b2g + e1 * T2 + tid);

    // zero x row 63 (both tiles)
    if (tid < 16) {
        uint32_t off = 63u * 256 + (uint32_t)((tid ^ 7) << 4);
        *(uint4*)(smem + SM_XH + off) = make_uint4(0, 0, 0, 0);
        *(uint4*)(smem + SM_XL + off) = make_uint4(0, 0, 0, 0);
    }
    // fill x rows 0..62, bf16 hi/lo split, swizzled
    if (tid < 252) {
        int r = tid >> 2, seg32 = (tid & 3) * 32;
        const float4* xr = (const float4*)(x + (b * 64 + 1 + r) * DD + seg32);
        #pragma unroll
        for (int j = 0; j < 8; j++) {
            float4 v = xr[j];
            int d = seg32 + j * 4;
            __nv_bfloat16 h0 = __float2bfloat16(v.x), h1 = __float2bfloat16(v.y);
            __nv_bfloat16 h2 = __float2bfloat16(v.z), h3 = __float2bfloat16(v.w);
            __nv_bfloat16 l0 = __float2bfloat16(v.x - __bfloat162float(h0));
            __nv_bfloat16 l1 = __float2bfloat16(v.y - __bfloat162float(h1));
            __nv_bfloat16 l2 = __float2bfloat16(v.z - __bfloat162float(h2));
            __nv_bfloat16 l3 = __float2bfloat16(v.w - __bfloat162float(h3));
            uint32_t off = (uint32_t)r * 256 + (uint32_t)((((d >> 3) ^ (r & 7)) << 4) + ((d * 2) & 15));
            *(__nv_bfloat162*)(smem + SM_XH + off)     = __halves2bfloat162(h0, h1);
            *(__nv_bfloat162*)(smem + SM_XH + off + 4) = __halves2bfloat162(h2, h3);
            *(__nv_bfloat162*)(smem + SM_XL + off)     = __halves2bfloat162(l0, l1);
            *(__nv_bfloat162*)(smem + SM_XL + off + 4) = __halves2bfloat162(l2, l3);
        }
    }
    __syncthreads();

    // prologue: B1(0), B2s0(0)->A, B2s1(0)->B
    load_b1t(sb, 0, e0, e1, tid); CP_COMMIT();
    load_b2t(sb, 0, 0, SM_B2A, e0, e1, tid); CP_COMMIT();
    load_b2t(sb, 0, 1, SM_B2B, e0, e1, tid); CP_COMMIT();

    // per-lane bases
    const int rA = wm * 16 + (t & 1) * 8 + r8;          // A rows (x and h)
    const uint32_t xbase = sb + SM_XH + (uint32_t)rA * 256;
    const uint32_t hbase = sb + SM_HH + (uint32_t)rA * 128;
    const int axor = rA & 7;
    const int rB0 = wn * 32 + (t >> 1) * 8 + r8;        // B1 rows (ntp adds 16)
    const int rW0 = wn * 80 + (t >> 1) * 8 + r8;        // B2 rows (ntp adds 16)

    float acc2[10][4];
    #pragma unroll
    for (int nt = 0; nt < 10; nt++)
        #pragma unroll
        for (int j = 0; j < 4; j++) acc2[nt][j] = 0.f;

    for (int ch = 0; ch < 8; ch++) {
        const int   e  = (ch >> 2) ? e1 : e0;
        const float g  = (ch >> 2) ? gt1 : gt0;
        const int   c4 = ch & 3;

        // ---- GEMM1 chunk (B1(ch) ready; s0,s1 still pending) ----
        CP_WAIT(2);
        __syncthreads();
        float acc1[4][4];
        #pragma unroll
        for (int nt = 0; nt < 4; nt++)
            #pragma unroll
            for (int j = 0; j < 4; j++) acc1[nt][j] = 0.f;

        #pragma unroll
        for (int ks = 0; ks < 8; ks++) {
            uint32_t ah[4], al[4];
            uint32_t sa = (uint32_t)(((2 * ks + (t >> 1)) ^ axor) << 4);
            ldsm4(ah, xbase + sa);
            ldsm4(al, xbase + 16384 + sa);
            #pragma unroll
            for (int ntp = 0; ntp < 2; ntp++) {
                int rB = rB0 + ntp * 16;
                uint32_t a = sb + SM_B1H + (uint32_t)rB * 256 +
                             (uint32_t)(((2 * ks + (t & 1)) ^ (rB & 7)) << 4);
                uint32_t bh[4], bl[4];
                ldsm4(bh, a);
                ldsm4(bl, a + 16384);
                mma16(acc1[ntp * 2],     ah, bh[0], bh[1]);
                mma16(acc1[ntp * 2],     al, bh[0], bh[1]);
                mma16(acc1[ntp * 2],     ah, bl[0], bl[1]);
                mma16(acc1[ntp * 2 + 1], ah, bh[2], bh[3]);
                mma16(acc1[ntp * 2 + 1], al, bh[2], bh[3]);
                mma16(acc1[ntp * 2 + 1], ah, bl[2], bl[3]);
            }
        }
        // ---- h epilogue: bias + relu + gate -> bf16 hi/lo (swizzled) ----
        #pragma unroll
        for (int nt = 0; nt < 4; nt++) {
            int col = wn * 32 + nt * 8 + p2;            // chunk-local 0..63
            float bv0 = __ldg(b1g + e * HH + c4 * 64 + col);
            float bv1 = __ldg(b1g + e * HH + c4 * 64 + col + 1);
            int r0 = wm * 16 + q, r1 = r0 + 8;
            float v00 = g * fmaxf(acc1[nt][0] + bv0, 0.f);
            float v01 = g * fmaxf(acc1[nt][1] + bv1, 0.f);
            float v10 = g * fmaxf(acc1[nt][2] + bv0, 0.f);
            float v11 = g * fmaxf(acc1[nt][3] + bv1, 0.f);
            __nv_bfloat16 a0 = __float2bfloat16(v00), a1 = __float2bfloat16(v01);
            __nv_bfloat16 c0 = __float2bfloat16(v10), c1 = __float2bfloat16(v11);
            uint32_t o0 = (uint32_t)r0 * 128 + (uint32_t)((((col >> 3) ^ (r0 & 7)) << 4) + ((col * 2) & 15));
            uint32_t o1 = (uint32_t)r1 * 128 + (uint32_t)((((col >> 3) ^ (r1 & 7)) << 4) + ((col * 2) & 15));
            *(__nv_bfloat162*)(smem + SM_HH + o0) = __halves2bfloat162(a0, a1);
            *(__nv_bfloat162*)(smem + SM_HH + o1) = __halves2bfloat162(c0, c1);
            *(__nv_bfloat162*)(smem + SM_HL + o0) = __halves2bfloat162(
                __float2bfloat16(v00 - __bfloat162float(a0)),
                __float2bfloat16(v01 - __bfloat162float(a1)));
            *(__nv_bfloat162*)(smem + SM_HL + o1) = __halves2bfloat162(
                __float2bfloat16(v10 - __bfloat162float(c0)),
                __float2bfloat16(v11 - __bfloat162float(c1)));
        }

        // ---- GEMM2: 4 k16 subs, buffers A,B alternating ----
        #pragma unroll
        for (int kt = 0; kt < 4; kt++) {
            if (kt == 0) { CP_WAIT(1); } else { CP_WAIT(2); }
            __syncthreads();   // sub tile ready; (kt==0 also: h visible, B1 free)
            uint32_t bufb = (kt & 1) ? (uint32_t)SM_B2B : (uint32_t)SM_B2A;
            uint32_t hah[4], hal[4];
            uint32_t sa = (uint32_t)(((kt * 2 + (t >> 1)) ^ axor) << 4);
            ldsm4(hah, hbase + sa);
            ldsm4(hal, hbase + 8192 + sa);
            #pragma unroll
            for (int ntp = 0; ntp < 5; ntp++) {
                int rW = rW0 + ntp * 16;
                uint32_t a = sb + bufb + (uint32_t)rW * 48 + (uint32_t)((t & 1) << 4);
                uint32_t bh[4], bl[4];
                ldsm4(bh, a);
                ldsm4(bl, a + 7680);
                mma16(acc2[ntp * 2],     hah, bh[0], bh[1]);
                mma16(acc2[ntp * 2],     hal, bh[0], bh[1]);
                mma16(acc2[ntp * 2],     hah, bl[0], bl[1]);
                mma16(acc2[ntp * 2 + 1], hah, bh[2], bh[3]);
                mma16(acc2[ntp * 2 + 1], hal, bh[2], bh[3]);
                mma16(acc2[ntp * 2 + 1], hah, bl[2], bl[3]);
            }
            __syncthreads();   // buffer free for refill
            if (kt == 0) {
                load_b2t(sb, ch, 2, SM_B2A, e0, e1, tid); CP_COMMIT();
            } else if (kt == 1) {
                load_b2t(sb, ch, 3, SM_B2B, e0, e1, tid); CP_COMMIT();
                load_b1t(sb, ch + 1, e0, e1, tid);        CP_COMMIT();
            } else if (kt == 2) {
                load_b2t(sb, ch + 1, 0, SM_B2A, e0, e1, tid); CP_COMMIT();
            } else {
                load_b2t(sb, ch + 1, 1, SM_B2B, e0, e1, tid); CP_COMMIT();
            }
        }
    }

    // ---- final epilogue: combined bias + store ----
    const float* bc = (const float*)(smem + SM_BIAS);
    int r0 = wm * 16 + q;
    #pragma unroll
    for (int nt = 0; nt < 10; nt++) {
        int col = wn * 80 + nt * 8 + p2;
        float bv0 = bc[col], bv1 = bc[col + 1];
        if (r0 < NTOK) {
            float2 v = make_float2(acc2[nt][0] + bv0, acc2[nt][1] + bv1);
            *(float2*)(out + (b * NTOK + r0) * T2 + col) = v;
        }
        if (r0 + 8 < NTOK) {
            float2 v = make_float2(acc2[nt][2] + bv0, acc2[nt][3] + bv1);
            *(float2*)(out + (b * NTOK + r0 + 8) * T2 + col) = v;
        }
    }
}

extern "C" void kernel_launch(void* const* d_in, const int* in_sizes, int n_in,
                              void* d_out, int out_size) {
    const float* x  = (const float*)d_in[0];
    const float* rw = (const float*)d_in[1];
    const float* rb = (const float*)d_in[2];
    const float* w1 = (const float*)d_in[3];
    const float* b1 = (const float*)d_in[4];
    const float* w2 = (const float*)d_in[5];
    const float* b2 = (const float*)d_in[6];
    float* out = (float*)d_out;

    prep_w<<<dim3(72, 1, EE), dim3(32, 8)>>>(w1, w2);
    router_kernel<<<BB, 128>>>(x, rw, rb);

    cudaFuncSetAttribute(moe_kernel, cudaFuncAttributeMaxDynamicSharedMemorySize, SM_TOT);
    moe_kernel<<<BB, 256, SM_TOT>>>(x, b1, b2, out);
}